// round 10
// baseline (speedup 1.0000x reference)
#include <cuda_runtime.h>
#include <cstdint>
#include <cstddef>

#define K_   512
#define D_   64
#define N_   262144
#define BM   128
#define THREADS 256

// ---- smem byte offsets (vq_main) ----
#define SMO_A     0            // [128][132B] bf16 z tile (32 u32 data + 1 pad per row)
#define SMO_B     16896        // [512][128B] bf16 codebook, XOR-swizzled rows
#define SMO_SQ    82432        // [128][1040B] bf16 q values (260 u32 stride, 256 used)
#define SMO_BSQ   215552       // [512] f32
#define SMO_ASQ   217600       // [128] f32
#define SMO_DLT   218112       // [128] f32
#define SMO_QMIN  218624       // [2][128] f32
#define SMO_BD    219648       // [2][128] f32
#define SMO_BI    220672       // [2][128] i32
#define SMO_SIDX  221696       // [128] i32
#define SMEM_MAIN 222208

// ---- device scratch ----
__device__ float g_bcs[K_];
__device__ float g_bes[K_ * D_];
__device__ float g_bsq[K_];
__device__ unsigned g_bbf[K_ * D_ / 2];  // codebook bf16 pairs, [k][dimpair] plain
__device__ float g_asq[N_];              // exact a_sq per point
__device__ unsigned g_cmaxbits;          // max_k bsq as float bits

// ---- helpers ----
__device__ __forceinline__ unsigned pack_bf16x2(float hi, float lo) {
    unsigned r;
    asm("cvt.rn.bf16x2.f32 %0, %1, %2;" : "=r"(r) : "f"(hi), "f"(lo));
    return r;
}
__device__ __forceinline__ void mma16816(float* c, const unsigned* a, const unsigned* b) {
    asm volatile(
        "mma.sync.aligned.m16n8k16.row.col.f32.bf16.bf16.f32 "
        "{%0,%1,%2,%3}, {%4,%5,%6,%7}, {%8,%9}, {%0,%1,%2,%3};"
        : "+f"(c[0]), "+f"(c[1]), "+f"(c[2]), "+f"(c[3])
        : "r"(a[0]), "r"(a[1]), "r"(a[2]), "r"(a[3]), "r"(b[0]), "r"(b[1]));
}
__device__ __forceinline__ float bf_lo(unsigned u) { return __uint_as_float(u << 16); }
__device__ __forceinline__ float bf_hi(unsigned u) { return __uint_as_float(u & 0xFFFF0000u); }

// ---------------- prep: bsq, bf16 codebook, cmax, zero accumulators ----------------
__global__ void vq_prep(const float* __restrict__ cb) {
    int i = blockIdx.x * blockDim.x + threadIdx.x;
    if (i < K_ * D_) g_bes[i] = 0.0f;
    if (i < K_ * D_ / 2) {
        g_bbf[i] = pack_bf16x2(cb[2 * i + 1], cb[2 * i]);   // hi = odd dim, lo = even dim
    }
    if (i < K_) {
        g_bcs[i] = 0.0f;
        const float* row = cb + i * D_;
        float s = 0.0f;  // reference: mul then add, ascending, NO fma
#pragma unroll
        for (int d = 0; d < D_; ++d) s = __fadd_rn(s, __fmul_rn(row[d], row[d]));
        g_bsq[i] = s;
        atomicMax(&g_cmaxbits, __float_as_uint(s));
    }
}

// ---------------- asq: exact per-point ||z||^2 (ascending mul+add) ----------------
extern __shared__ float smem_a[];
__global__ void vq_asq(const float* __restrict__ z) {
    const int tid = threadIdx.x;
    const size_t base = (size_t)blockIdx.x * 256 * D_;
    // stage [256][65] to make row reads conflict-free
    for (int it = 0; it < 64; ++it) {
        int idx = it * 256 + tid;
        smem_a[(idx >> 6) * 65 + (idx & 63)] = z[base + idx];
    }
    __syncthreads();
    float a = 0.0f;
    const float* r = smem_a + tid * 65;
#pragma unroll
    for (int d = 0; d < D_; ++d) a = __fadd_rn(a, __fmul_rn(r[d], r[d]));
    g_asq[blockIdx.x * 256 + tid] = a;
}

// ---------------- main ----------------
extern __shared__ char smem[];

__global__ void __launch_bounds__(THREADS, 1) vq_main(
    const float* __restrict__ z, const float* __restrict__ cb,
    float* __restrict__ o_zq, float* __restrict__ o_idx, float* __restrict__ o_mind)
{
    const int tid = threadIdx.x;
    const int wid = tid >> 5, lane = tid & 31;
    const int gid = lane >> 2, tig = lane & 3;     // mma group / thread-in-group
    const int p0 = blockIdx.x * BM;

    unsigned* sA  = (unsigned*)(smem + SMO_A);     // row stride 33 u32
    unsigned* sB  = (unsigned*)(smem + SMO_B);     // row stride 32 u32, swizzled
    unsigned* sQ  = (unsigned*)(smem + SMO_SQ);    // row stride 260 u32
    float* sbsq = (float*)(smem + SMO_BSQ);
    float* sasq = (float*)(smem + SMO_ASQ);
    float* sdlt = (float*)(smem + SMO_DLT);
    float* sqmin = (float*)(smem + SMO_QMIN);
    float* sbd  = (float*)(smem + SMO_BD);
    int*   sbi  = (int*)(smem + SMO_BI);
    int*   sidx = (int*)(smem + SMO_SIDX);

    // A fill: z f32 pairs -> bf16x2, [point][dimpair], stride 33 u32
    {
        const float2* z2 = (const float2*)(z + (size_t)p0 * D_);
        for (int i = tid; i < BM * 32; i += THREADS) {
            float2 v = z2[i];
            sA[(i >> 5) * 33 + (i & 31)] = pack_bf16x2(v.y, v.x);
        }
    }
    // B copy with XOR swizzle: dst u32 = row*32 + (x ^ ((row&7)<<2)); float4 granules stay intact
    {
        const float4* gb4 = (const float4*)g_bbf;
        for (int i4 = tid; i4 < K_ * 8; i4 += THREADS) {   // 4096 float4
            int row = i4 >> 3, x4 = (i4 & 7) << 2;
            float4 v = gb4[i4];
            *(float4*)(sB + row * 32 + (x4 ^ ((row & 7) << 2))) = v;
        }
        for (int i = tid; i < K_; i += THREADS) sbsq[i] = g_bsq[i];
    }
    // exact asq + margin
    if (tid < BM) {
        float a = g_asq[p0 + tid];
        sasq[tid] = a;
        float cmax = __uint_as_float(g_cmaxbits);
        float rt = sqrtf(a * cmax);
        sdlt[tid] = 0.03125f * rt + 0.0078125f * (cmax + 2.0f * rt) + 1e-3f;
    }
    __syncthreads();

    // ---- load A fragments once per warp (points 16*wid .. 16*wid+15) ----
    unsigned af[4][4];
#pragma unroll
    for (int ks = 0; ks < 4; ++ks) {
        int r0 = (16 * wid + gid) * 33, r1 = (16 * wid + gid + 8) * 33;
        int x = tig + 8 * ks;
        af[ks][0] = sA[r0 + x];
        af[ks][1] = sA[r1 + x];
        af[ks][2] = sA[r0 + x + 4];
        af[ks][3] = sA[r1 + x + 4];
    }

    // ---- GEMM: 64 n-tiles of 8 codes, paired for pipelining; q -> sQ ----
    const int gx = gid << 2;
    for (int nc = 0; nc < 64; nc += 2) {
        float acc[2][4] = {{0.f, 0.f, 0.f, 0.f}, {0.f, 0.f, 0.f, 0.f}};
#pragma unroll
        for (int ks = 0; ks < 4; ++ks) {
#pragma unroll
            for (int u = 0; u < 2; ++u) {
                int crow = ((nc + u) * 8 + gid) * 32;
                int x0 = tig + 8 * ks;
                unsigned b[2];
                b[0] = sB[crow + (x0 ^ gx)];
                b[1] = sB[crow + ((x0 + 4) ^ gx)];
                mma16816(acc[u], af[ks], b);
            }
        }
#pragma unroll
        for (int u = 0; u < 2; ++u) {
            float2 bs = *(const float2*)(sbsq + (nc + u) * 8 + 2 * tig);
            float q0 = __fmaf_rn(-2.0f, acc[u][0], bs.x);
            float q1 = __fmaf_rn(-2.0f, acc[u][1], bs.y);
            float q2 = __fmaf_rn(-2.0f, acc[u][2], bs.x);
            float q3 = __fmaf_rn(-2.0f, acc[u][3], bs.y);
            int jpos = (nc + u) * 4 + tig;
            sQ[(16 * wid + gid) * 260 + jpos]     = pack_bf16x2(q1, q0);
            sQ[(16 * wid + gid + 8) * 260 + jpos] = pack_bf16x2(q3, q2);
        }
    }
    __syncthreads();

    // ---- scan pass 1: per (point, half) qmin over 128 u32 (rotated start, conflict-free) ----
    const int sp = tid >> 1, sh = tid & 1;
    const unsigned* qrow = sQ + sp * 260 + sh * 128;
    const int srot = 2 * ((sp >> 3) & 1) + sh;
    {
        float qmin = 3.4e38f;
        for (int jj = 0; jj < 128; ++jj) {
            unsigned u = qrow[(srot + jj) & 127];
            qmin = fminf(qmin, fminf(bf_lo(u), bf_hi(u)));
        }
        sqmin[sh * BM + sp] = qmin;
    }
    __syncthreads();

    // ---- scan pass 2: candidates within margin -> exact verify (reference-rounded) ----
    {
        float T = fminf(sqmin[sp], sqmin[BM + sp]) + sdlt[sp];
        float asq = sasq[sp];
        float bestD = 3.4e38f;
        int   bestI = 0x7fffffff;
        const float* zr = z + (size_t)(p0 + sp) * D_;
        for (int jj = 0; jj < 128; ++jj) {
            int j = (srot + jj) & 127;
            unsigned u = qrow[j];
            float qlo = bf_lo(u), qhi = bf_hi(u);
            if (fminf(qlo, qhi) <= T) {
                int cp = sh * 128 + j;
#pragma unroll
                for (int e = 0; e < 2; ++e) {
                    float qv = e ? qhi : qlo;
                    if (qv <= T) {
                        int k = 2 * cp + e;
                        const float* cr = cb + k * D_;
                        float dot = 0.0f;
#pragma unroll 8
                        for (int d = 0; d < D_; ++d) dot = __fmaf_rn(zr[d], cr[d], dot);
                        float de = __fadd_rn(__fmaf_rn(-2.0f, dot, asq), sbsq[k]);
                        if (de < bestD || (de == bestD && k < bestI)) { bestD = de; bestI = k; }
                    }
                }
            }
        }
        sbd[sh * BM + sp] = bestD;
        sbi[sh * BM + sp] = bestI;
    }
    __syncthreads();

    // ---- merge halves, outputs, cluster-size atomic ----
    if (tid < BM) {
        float d0 = sbd[tid], d1 = sbd[BM + tid];
        int   i0 = sbi[tid], i1 = sbi[BM + tid];
        float bv = d0; int bi = i0;
        if (d1 < bv || (d1 == bv && i1 < bi)) { bv = d1; bi = i1; }
        o_idx[p0 + tid] = (float)bi;
        o_mind[p0 + tid] = bv;
        sidx[tid] = bi;
        atomicAdd(&g_bcs[bi], 1.0f);
    }
    __syncthreads();

    // ---- z_q_st (z_e + (z_q - z_e), non-fused) + embedding-sum scatter ----
    for (int i = tid; i < BM * D_; i += THREADS) {
        int p = i >> 6, d = i & 63;
        int bi = sidx[p];
        float ze = z[(size_t)p0 * D_ + i];
        float zq = cb[bi * D_ + d];
        o_zq[(size_t)p0 * D_ + i] = __fadd_rn(ze, __fsub_rn(zq, ze));
        atomicAdd(&g_bes[bi * D_ + d], ze);
    }
}

// ---------------- finalize: EMA update + new codebook ----------------
__global__ void vq_final(const float* __restrict__ ema_cs, const float* __restrict__ ema_es,
                         float* __restrict__ o_cb, float* __restrict__ o_cs,
                         float* __restrict__ o_es)
{
    int i = blockIdx.x * blockDim.x + threadIdx.x;
    if (i < K_) {
        o_cs[i] = __fadd_rn(__fmul_rn(0.99f, ema_cs[i]), __fmul_rn(0.01f, g_bcs[i]));
    }
    if (i < K_ * D_) {
        int k = i / D_;
        float ncs = __fadd_rn(__fmul_rn(0.99f, ema_cs[k]), __fmul_rn(0.01f, g_bcs[k]));
        float nes = __fadd_rn(__fmul_rn(0.99f, ema_es[i]), __fmul_rn(0.01f, g_bes[i]));
        o_es[i] = nes;
        o_cb[i] = __fdiv_rn(nes, __fadd_rn(ncs, 1e-5f));
    }
}

// ---------------- launcher ----------------
extern "C" void kernel_launch(void* const* d_in, const int* in_sizes, int n_in,
                              void* d_out, int out_size)
{
    const float* z      = (const float*)d_in[0];
    const float* cb     = (const float*)d_in[1];
    const float* ema_cs = (const float*)d_in[2];
    const float* ema_es = (const float*)d_in[3];

    float* out    = (float*)d_out;
    float* o_zq   = out;
    float* o_idx  = o_zq + (size_t)N_ * D_;
    float* o_mind = o_idx + N_;
    float* o_cb   = o_mind + N_;
    float* o_cs   = o_cb + (size_t)K_ * D_;
    float* o_es   = o_cs + K_;

    (void)in_sizes; (void)n_in; (void)out_size;

    vq_prep<<<(K_ * D_ + 255) / 256, 256>>>(cb);

    const int smem_asq = 256 * 65 * 4;  // 66,560 B
    cudaFuncSetAttribute(vq_asq, cudaFuncAttributeMaxDynamicSharedMemorySize, smem_asq);
    vq_asq<<<N_ / 256, 256, smem_asq>>>(z);

    cudaFuncSetAttribute(vq_main, cudaFuncAttributeMaxDynamicSharedMemorySize, SMEM_MAIN);
    vq_main<<<N_ / BM, THREADS, SMEM_MAIN>>>(z, cb, o_zq, o_idx, o_mind);

    vq_final<<<(K_ * D_ + 255) / 256, 256>>>(ema_cs, ema_es, o_cb, o_cs, o_es);
}

// round 11
// speedup vs baseline: 1.7111x; 1.7111x over previous
#include <cuda_runtime.h>
#include <cstdint>
#include <cstddef>

#define K_   512
#define D_   64
#define N_   262144
#define BM   128
#define THREADS 256
#define CAP  3840   // candidate list capacity

// ---- smem byte offsets (vq_main) ----
#define SMO_A     0            // [128][132B] bf16 z tile (32 u32 + 1 pad per row); dead after frag load
#define SMO_B     16896        // [512][128B] bf16 codebook, XOR-swizzled rows
#define SMO_SQ    82432        // [128][1040B] bf16 q values (260 u32 stride, 256 used)
#define SMO_BSQ   215552       // [512] f32
#define SMO_ASQ   217600       // [128] f32
#define SMO_DLT   218112       // [128] f32
#define SMO_T     218624       // [128] f32 threshold
#define SMO_CNT   219136       // counter + pad
#define SMEM_MAIN 219200
// aliased over SMO_A after GEMM:
#define SMO_LIST  0            // [3840] u32 candidates
#define SMO_BEST  15360        // [128] u64 packed (dist_bits<<32)|k
#define SMO_SIDX  16384        // [128] i32 winner

// ---- device scratch ----
__device__ float g_bcs[K_];
__device__ float g_bes[K_ * D_];
__device__ float g_bsq[K_];
__device__ unsigned g_bbf[K_ * D_ / 2];  // codebook bf16 pairs
__device__ float g_asq[N_];              // exact a_sq per point
__device__ unsigned g_cmaxbits;

// ---- helpers ----
__device__ __forceinline__ unsigned pack_bf16x2(float hi, float lo) {
    unsigned r;
    asm("cvt.rn.bf16x2.f32 %0, %1, %2;" : "=r"(r) : "f"(hi), "f"(lo));
    return r;
}
__device__ __forceinline__ void mma16816(float* c, const unsigned* a, const unsigned* b) {
    asm volatile(
        "mma.sync.aligned.m16n8k16.row.col.f32.bf16.bf16.f32 "
        "{%0,%1,%2,%3}, {%4,%5,%6,%7}, {%8,%9}, {%0,%1,%2,%3};"
        : "+f"(c[0]), "+f"(c[1]), "+f"(c[2]), "+f"(c[3])
        : "r"(a[0]), "r"(a[1]), "r"(a[2]), "r"(a[3]), "r"(b[0]), "r"(b[1]));
}
__device__ __forceinline__ float bf_lo(unsigned u) { return __uint_as_float(u << 16); }
__device__ __forceinline__ float bf_hi(unsigned u) { return __uint_as_float(u & 0xFFFF0000u); }

// exact reference-rounded distance + lexicographic publish
__device__ __forceinline__ void verify_cand(
    const float* __restrict__ z, const float* __restrict__ cb,
    const float* sasq, const float* sbsq, unsigned long long* sbest,
    int p0, int p, int k)
{
    const float* zr = z + (size_t)(p0 + p) * D_;
    const float* cr = cb + (size_t)k * D_;
    float dot = 0.0f;
#pragma unroll 16
    for (int d = 0; d < D_; ++d) dot = __fmaf_rn(zr[d], cr[d], dot);
    float de = __fadd_rn(__fmaf_rn(-2.0f, dot, sasq[p]), sbsq[k]);
    unsigned long long pk = ((unsigned long long)__float_as_uint(de) << 32) | (unsigned)k;
    atomicMin(&sbest[p], pk);
}

// ---------------- prep ----------------
__global__ void vq_prep(const float* __restrict__ cb) {
    int i = blockIdx.x * blockDim.x + threadIdx.x;
    if (i < K_ * D_) g_bes[i] = 0.0f;
    if (i < K_ * D_ / 2) g_bbf[i] = pack_bf16x2(cb[2 * i + 1], cb[2 * i]);
    if (i < K_) {
        g_bcs[i] = 0.0f;
        const float* row = cb + i * D_;
        float s = 0.0f;  // reference: mul then add, ascending, NO fma
#pragma unroll
        for (int d = 0; d < D_; ++d) s = __fadd_rn(s, __fmul_rn(row[d], row[d]));
        g_bsq[i] = s;
        atomicMax(&g_cmaxbits, __float_as_uint(s));
    }
}

// ---------------- asq: exact per-point ||z||^2 (ascending mul+add) ----------------
extern __shared__ float smem_a[];
__global__ void vq_asq(const float* __restrict__ z) {
    const int tid = threadIdx.x;
    const size_t base = (size_t)blockIdx.x * 256 * D_;
    for (int it = 0; it < 64; ++it) {
        int idx = it * 256 + tid;
        smem_a[(idx >> 6) * 65 + (idx & 63)] = z[base + idx];
    }
    __syncthreads();
    float a = 0.0f;
    const float* r = smem_a + tid * 65;
#pragma unroll
    for (int d = 0; d < D_; ++d) a = __fadd_rn(a, __fmul_rn(r[d], r[d]));
    g_asq[blockIdx.x * 256 + tid] = a;
}

// ---------------- main ----------------
extern __shared__ char smem[];

__global__ void __launch_bounds__(THREADS, 1) vq_main(
    const float* __restrict__ z, const float* __restrict__ cb,
    float* __restrict__ o_zq, float* __restrict__ o_idx, float* __restrict__ o_mind)
{
    const int tid = threadIdx.x;
    const int wid = tid >> 5, lane = tid & 31;
    const int gid = lane >> 2, tig = lane & 3;
    const int p0 = blockIdx.x * BM;

    unsigned* sA  = (unsigned*)(smem + SMO_A);
    unsigned* sB  = (unsigned*)(smem + SMO_B);
    unsigned* sQ  = (unsigned*)(smem + SMO_SQ);
    float* sbsq = (float*)(smem + SMO_BSQ);
    float* sasq = (float*)(smem + SMO_ASQ);
    float* sdlt = (float*)(smem + SMO_DLT);
    float* sT   = (float*)(smem + SMO_T);
    int*   scnt = (int*)(smem + SMO_CNT);
    unsigned* slist = (unsigned*)(smem + SMO_LIST);
    unsigned long long* sbest = (unsigned long long*)(smem + SMO_BEST);
    int* sidx = (int*)(smem + SMO_SIDX);

    // ---- phase 0: fills ----
    {
        const float2* z2 = (const float2*)(z + (size_t)p0 * D_);
        for (int i = tid; i < BM * 32; i += THREADS) {
            float2 v = z2[i];
            sA[(i >> 5) * 33 + (i & 31)] = pack_bf16x2(v.y, v.x);
        }
        const float4* gb4 = (const float4*)g_bbf;
        for (int i4 = tid; i4 < K_ * 8; i4 += THREADS) {
            int row = i4 >> 3, x4 = (i4 & 7) << 2;
            float4 v = gb4[i4];
            *(float4*)(sB + row * 32 + (x4 ^ ((row & 7) << 2))) = v;
        }
        for (int i = tid; i < K_; i += THREADS) sbsq[i] = g_bsq[i];
    }
    if (tid < BM) {
        float a = g_asq[p0 + tid];
        sasq[tid] = a;
        float cmax = __uint_as_float(g_cmaxbits);
        float rt = sqrtf(a * cmax);
        sdlt[tid] = 0.03125f * rt + 0.0078125f * (cmax + 2.0f * rt) + 1e-3f;
    }
    __syncthreads();

    // ---- A fragments (points 16*wid .. 16*wid+15) ----
    unsigned af[4][4];
#pragma unroll
    for (int ks = 0; ks < 4; ++ks) {
        int r0 = (16 * wid + gid) * 33, r1 = (16 * wid + gid + 8) * 33;
        int x = tig + 8 * ks;
        af[ks][0] = sA[r0 + x];
        af[ks][1] = sA[r1 + x];
        af[ks][2] = sA[r0 + x + 4];
        af[ks][3] = sA[r1 + x + 4];
    }

    // ---- GEMM + fused per-point qmin ----
    const int gx = gid << 2;
    float qr0 = 3.4e38f, qr1 = 3.4e38f;
    for (int nc = 0; nc < 64; nc += 2) {
        float acc[2][4] = {{0.f, 0.f, 0.f, 0.f}, {0.f, 0.f, 0.f, 0.f}};
#pragma unroll
        for (int ks = 0; ks < 4; ++ks) {
#pragma unroll
            for (int u = 0; u < 2; ++u) {
                int crow = ((nc + u) * 8 + gid) * 32;
                int x0 = tig + 8 * ks;
                unsigned b[2];
                b[0] = sB[crow + (x0 ^ gx)];
                b[1] = sB[crow + ((x0 + 4) ^ gx)];
                mma16816(acc[u], af[ks], b);
            }
        }
#pragma unroll
        for (int u = 0; u < 2; ++u) {
            float2 bs = *(const float2*)(sbsq + (nc + u) * 8 + 2 * tig);
            float q0 = __fmaf_rn(-2.0f, acc[u][0], bs.x);
            float q1 = __fmaf_rn(-2.0f, acc[u][1], bs.y);
            float q2 = __fmaf_rn(-2.0f, acc[u][2], bs.x);
            float q3 = __fmaf_rn(-2.0f, acc[u][3], bs.y);
            qr0 = fminf(qr0, fminf(q0, q1));
            qr1 = fminf(qr1, fminf(q2, q3));
            int jpos = (nc + u) * 4 + tig;
            sQ[(16 * wid + gid) * 260 + jpos]     = pack_bf16x2(q1, q0);
            sQ[(16 * wid + gid + 8) * 260 + jpos] = pack_bf16x2(q3, q2);
        }
    }
    // reduce qmin over the 4-lane group; tig==0 writes thresholds
    qr0 = fminf(qr0, __shfl_xor_sync(0xFFFFFFFFu, qr0, 1));
    qr0 = fminf(qr0, __shfl_xor_sync(0xFFFFFFFFu, qr0, 2));
    qr1 = fminf(qr1, __shfl_xor_sync(0xFFFFFFFFu, qr1, 1));
    qr1 = fminf(qr1, __shfl_xor_sync(0xFFFFFFFFu, qr1, 2));
    if (tig == 0) {
        int r0 = 16 * wid + gid, r1 = r0 + 8;
        sT[r0] = qr0 + sdlt[r0];
        sT[r1] = qr1 + sdlt[r1];
    }
    __syncthreads();   // sQ, sT complete; sA dead -> init aliased structures

    if (tid == 0) scnt[0] = 0;
    if (tid < BM) sbest[tid] = 0xFFFFFFFFFFFFFFFFull;
    __syncthreads();

    // ---- scan: append candidates (q_bf16 <= T) ----
    {
        const int sp = tid >> 1, sh = tid & 1;
        const unsigned* qrow = sQ + sp * 260 + sh * 128;
        const int srot = 2 * ((sp >> 3) & 1) + sh;
        float T = sT[sp];
        for (int jj = 0; jj < 128; ++jj) {
            int j = (srot + jj) & 127;
            unsigned u = qrow[j];
            float qlo = bf_lo(u), qhi = bf_hi(u);
            if (fminf(qlo, qhi) <= T) {
                int jpos = sh * 128 + j;
                int kbase = 8 * (jpos >> 2) + 2 * (jpos & 3);
#pragma unroll
                for (int e = 0; e < 2; ++e) {
                    if ((e ? qhi : qlo) <= T) {
                        int slot = atomicAdd(scnt, 1);
                        if (slot < CAP) slist[slot] = ((unsigned)sp << 16) | (unsigned)(kbase + e);
                        else verify_cand(z, cb, sasq, sbsq, sbest, p0, sp, kbase + e);
                    }
                }
            }
        }
    }
    __syncthreads();

    // ---- cooperative exact verify ----
    {
        int m = scnt[0]; if (m > CAP) m = CAP;
        for (int ci = tid; ci < m; ci += THREADS) {
            unsigned e = slist[ci];
            verify_cand(z, cb, sasq, sbsq, sbest, p0, (int)(e >> 16), (int)(e & 0xFFFF));
        }
    }
    __syncthreads();

    // ---- outputs + cluster-size atomic ----
    if (tid < BM) {
        unsigned long long pk = sbest[tid];
        int bi = (int)(pk & 0xFFFFFFFFu);
        o_idx[p0 + tid] = (float)bi;
        o_mind[p0 + tid] = __uint_as_float((unsigned)(pk >> 32));
        sidx[tid] = bi;
        atomicAdd(&g_bcs[bi], 1.0f);
    }
    __syncthreads();

    // ---- z_q_st (z_e + (z_q - z_e), non-fused) + embedding-sum scatter ----
    for (int i = tid; i < BM * D_; i += THREADS) {
        int p = i >> 6, d = i & 63;
        int bi = sidx[p];
        float ze = z[(size_t)p0 * D_ + i];
        float zq = cb[bi * D_ + d];
        o_zq[(size_t)p0 * D_ + i] = __fadd_rn(ze, __fsub_rn(zq, ze));
        atomicAdd(&g_bes[bi * D_ + d], ze);
    }
}

// ---------------- finalize ----------------
__global__ void vq_final(const float* __restrict__ ema_cs, const float* __restrict__ ema_es,
                         float* __restrict__ o_cb, float* __restrict__ o_cs,
                         float* __restrict__ o_es)
{
    int i = blockIdx.x * blockDim.x + threadIdx.x;
    if (i < K_) {
        o_cs[i] = __fadd_rn(__fmul_rn(0.99f, ema_cs[i]), __fmul_rn(0.01f, g_bcs[i]));
    }
    if (i < K_ * D_) {
        int k = i / D_;
        float ncs = __fadd_rn(__fmul_rn(0.99f, ema_cs[k]), __fmul_rn(0.01f, g_bcs[k]));
        float nes = __fadd_rn(__fmul_rn(0.99f, ema_es[i]), __fmul_rn(0.01f, g_bes[i]));
        o_es[i] = nes;
        o_cb[i] = __fdiv_rn(nes, __fadd_rn(ncs, 1e-5f));
    }
}

// ---------------- launcher ----------------
extern "C" void kernel_launch(void* const* d_in, const int* in_sizes, int n_in,
                              void* d_out, int out_size)
{
    const float* z      = (const float*)d_in[0];
    const float* cb     = (const float*)d_in[1];
    const float* ema_cs = (const float*)d_in[2];
    const float* ema_es = (const float*)d_in[3];

    float* out    = (float*)d_out;
    float* o_zq   = out;
    float* o_idx  = o_zq + (size_t)N_ * D_;
    float* o_mind = o_idx + N_;
    float* o_cb   = o_mind + N_;
    float* o_cs   = o_cb + (size_t)K_ * D_;
    float* o_es   = o_cs + K_;

    (void)in_sizes; (void)n_in; (void)out_size;

    vq_prep<<<(K_ * D_ + 255) / 256, 256>>>(cb);

    const int smem_asq = 256 * 65 * 4;
    cudaFuncSetAttribute(vq_asq, cudaFuncAttributeMaxDynamicSharedMemorySize, smem_asq);
    vq_asq<<<N_ / 256, 256, smem_asq>>>(z);

    cudaFuncSetAttribute(vq_main, cudaFuncAttributeMaxDynamicSharedMemorySize, SMEM_MAIN);
    vq_main<<<N_ / BM, THREADS, SMEM_MAIN>>>(z, cb, o_zq, o_idx, o_mind);

    vq_final<<<(K_ * D_ + 255) / 256, 256>>>(ema_cs, ema_es, o_cb, o_cs, o_es);
}